// round 1
// baseline (speedup 1.0000x reference)
#include <cuda_runtime.h>
#include <math.h>

#define GX 200
#define GY 200
#define GZ 16
#define NVOX (GX*GY*GZ)
#define F_N 8

__device__ __forceinline__ void red_add_v4(float* p, float a, float b, float c, float d) {
#if __CUDA_ARCH__ >= 900
    asm volatile("red.global.add.v4.f32 [%0], {%1,%2,%3,%4};"
                 :: "l"(p), "f"(a), "f"(b), "f"(c), "f"(d) : "memory");
#else
    atomicAdd(p + 0, a); atomicAdd(p + 1, b);
    atomicAdd(p + 2, c); atomicAdd(p + 3, d);
#endif
}

__global__ void gv_zero_kernel(float4* out, int n4) {
    int i = blockIdx.x * blockDim.x + threadIdx.x;
    if (i < n4) out[i] = make_float4(0.f, 0.f, 0.f, 0.f);
}

__global__ void gv_splat_kernel(const float* __restrict__ means,
                                const float* __restrict__ opac,
                                const float* __restrict__ cov,
                                const float* __restrict__ feat,
                                float* __restrict__ out,
                                int G) {
    int gwarp = (blockIdx.x * blockDim.x + threadIdx.x) >> 5;
    if (gwarp >= G) return;
    int lane = threadIdx.x & 31;

    const float lox = -40.f, loy = -40.f, loz = -1.f;
    const float hix =  40.f, hiy =  40.f, hiz =  5.4f;
    const float VOX = 0.4f;

    float mx = means[gwarp*3 + 0];
    float my = means[gwarp*3 + 1];
    float mz = means[gwarp*3 + 2];
    const float* C = cov + (size_t)gwarp * 9;
    float c00 = C[0], c01 = C[1], c02 = C[2];
    float c11 = C[4], c12 = C[5], c22 = C[8];

    float sx = sqrtf(c00), sy = sqrtf(c11), sz = sqrtf(c22);
    float blx = mx - 3.f*sx, bly = my - 3.f*sy, blz = mz - 3.f*sz;
    float bhx = mx + 3.f*sx, bhy = my + 3.f*sy, bhz = mz + 3.f*sz;

    bool valid = (bhx > lox) && (bhy > loy) && (bhz > loz) &&
                 (blx < hix) && (bly < hiy) && (blz < hiz);
    if (!valid) return;

    float blxc = fminf(fmaxf(blx, lox), hix);
    float blyc = fminf(fmaxf(bly, loy), hiy);
    float blzc = fminf(fmaxf(blz, loz), hiz);
    float bhxc = fminf(fmaxf(bhx, lox), hix);
    float bhyc = fminf(fmaxf(bhy, loy), hiy);
    float bhzc = fminf(fmaxf(bhz, loz), hiz);

    int ilox = min((int)((blxc - lox) / VOX), GX - 1);
    int iloy = min((int)((blyc - loy) / VOX), GY - 1);
    int iloz = min((int)((blzc - loz) / VOX), GZ - 1);
    int ihix = min((int)((bhxc - lox) / VOX), GX - 1);
    int ihiy = min((int)((bhyc - loy) / VOX), GY - 1);
    int ihiz = min((int)((bhzc - loz) / VOX), GZ - 1);

    int nx = ihix - ilox + 1;
    int ny = ihiy - iloy + 1;
    int nz = ihiz - iloz + 1;

    // symmetric 3x3 inverse (adjugate / det)
    float i00 = c11*c22 - c12*c12;
    float i01 = c02*c12 - c01*c22;
    float i02 = c01*c12 - c02*c11;
    float i11 = c00*c22 - c02*c02;
    float i12 = c01*c02 - c00*c12;
    float i22 = c00*c11 - c01*c01;
    float det = c00*i00 + c01*i01 + c02*i02;
    float rdet = 1.f / det;
    float a00 = i00*rdet, a01 = i01*rdet, a02 = i02*rdet;
    float a11 = i11*rdet, a12 = i12*rdet, a22 = i22*rdet;

    float op = opac[gwarp];
    float f[F_N];
#pragma unroll
    for (int k = 0; k < F_N; k++) f[k] = feat[(size_t)gwarp*F_N + k];

    float* dgrid = out;
    float* fgrid = out + NVOX;

    int npairs = nx * ny;
    for (int p = lane; p < npairs; p += 32) {
        int ox = p / ny;
        int oy = p - ox * ny;
        int ix = ilox + ox;
        int iy = iloy + oy;
        float dx = ((float)ix + 0.5f) * VOX + lox - mx;
        float dy = ((float)iy + 0.5f) * VOX + loy - my;
        float cxy  = a00*dx*dx + a11*dy*dy + 2.f*a01*dx*dy;
        float clin = 2.f*(a02*dx + a12*dy);
        int flatBase = (ix * GY + iy) * GZ + iloz;
        for (int oz = 0; oz < nz; oz++) {
            int iz = iloz + oz;
            float dz = ((float)iz + 0.5f) * VOX + loz - mz;
            float maha = cxy + dz * (clin + a22 * dz);
            float dv = op * __expf(-0.5f * maha);
            atomicAdd(dgrid + flatBase + oz, dv);
            float* fp = fgrid + (size_t)(flatBase + oz) * F_N;
            red_add_v4(fp,     dv*f[0], dv*f[1], dv*f[2], dv*f[3]);
            red_add_v4(fp + 4, dv*f[4], dv*f[5], dv*f[6], dv*f[7]);
        }
    }
}

__global__ void gv_norm_kernel(float* __restrict__ out) {
    int v = blockIdx.x * blockDim.x + threadIdx.x;
    if (v >= NVOX) return;
    float den = out[v];
    float s = 1.f / fmaxf(den, 1e-6f);
    float4* fp = (float4*)(out + NVOX + (size_t)v * F_N);
    float4 a = fp[0], b = fp[1];
    a.x *= s; a.y *= s; a.z *= s; a.w *= s;
    b.x *= s; b.y *= s; b.z *= s; b.w *= s;
    fp[0] = a; fp[1] = b;
}

extern "C" void kernel_launch(void* const* d_in, const int* in_sizes, int n_in,
                              void* d_out, int out_size) {
    const float* means = (const float*)d_in[0];   // (G,3)
    const float* opac  = (const float*)d_in[1];   // (G,1)
    const float* cov   = (const float*)d_in[2];   // (G,3,3)
    const float* feat  = (const float*)d_in[3];   // (G,8)
    float* out = (float*)d_out;                   // [640000 density | 5120000 feats]

    int G = in_sizes[0] / 3;

    int n4 = out_size / 4;
    gv_zero_kernel<<<(n4 + 255) / 256, 256>>>((float4*)out, n4);

    int threads = G * 32;  // one warp per gaussian
    gv_splat_kernel<<<(threads + 255) / 256, 256>>>(means, opac, cov, feat, out, G);

    gv_norm_kernel<<<(NVOX + 255) / 256, 256>>>(out);
}

// round 2
// speedup vs baseline: 1.0127x; 1.0127x over previous
#include <cuda_runtime.h>
#include <math.h>

#define GX 200
#define GY 200
#define GZ 16
#define NVOX (GX*GY*GZ)
#define F_N 8

__device__ __forceinline__ void red_add_v4(float* p, float a, float b, float c, float d) {
#if __CUDA_ARCH__ >= 900
    asm volatile("red.global.add.v4.f32 [%0], {%1,%2,%3,%4};"
                 :: "l"(p), "f"(a), "f"(b), "f"(c), "f"(d) : "memory");
#else
    atomicAdd(p + 0, a); atomicAdd(p + 1, b);
    atomicAdd(p + 2, c); atomicAdd(p + 3, d);
#endif
}

__global__ void gv_zero_kernel(float4* out, int n4) {
    int i = blockIdx.x * blockDim.x + threadIdx.x;
    if (i < n4) out[i] = make_float4(0.f, 0.f, 0.f, 0.f);
}

__global__ void gv_splat_kernel(const float* __restrict__ means,
                                const float* __restrict__ opac,
                                const float* __restrict__ cov,
                                const float* __restrict__ feat,
                                float* __restrict__ out,
                                int G) {
    int gwarp = (blockIdx.x * blockDim.x + threadIdx.x) >> 5;
    if (gwarp >= G) return;
    int lane = threadIdx.x & 31;

    const float lox = -40.f, loy = -40.f, loz = -1.f;
    const float hix =  40.f, hiy =  40.f, hiz =  5.4f;
    const float VOX = 0.4f;

    float mx = means[gwarp*3 + 0];
    float my = means[gwarp*3 + 1];
    float mz = means[gwarp*3 + 2];
    const float* C = cov + (size_t)gwarp * 9;
    float c00 = C[0], c01 = C[1], c02 = C[2];
    float c11 = C[4], c12 = C[5], c22 = C[8];

    float sx = sqrtf(c00), sy = sqrtf(c11), sz = sqrtf(c22);
    float blx = mx - 3.f*sx, bly = my - 3.f*sy, blz = mz - 3.f*sz;
    float bhx = mx + 3.f*sx, bhy = my + 3.f*sy, bhz = mz + 3.f*sz;

    bool valid = (bhx > lox) && (bhy > loy) && (bhz > loz) &&
                 (blx < hix) && (bly < hiy) && (blz < hiz);
    if (!valid) return;

    float blxc = fminf(fmaxf(blx, lox), hix);
    float blyc = fminf(fmaxf(bly, loy), hiy);
    float blzc = fminf(fmaxf(blz, loz), hiz);
    float bhxc = fminf(fmaxf(bhx, lox), hix);
    float bhyc = fminf(fmaxf(bhy, loy), hiy);
    float bhzc = fminf(fmaxf(bhz, loz), hiz);

    int ilox = min((int)((blxc - lox) / VOX), GX - 1);
    int iloy = min((int)((blyc - loy) / VOX), GY - 1);
    int iloz = min((int)((blzc - loz) / VOX), GZ - 1);
    int ihix = min((int)((bhxc - lox) / VOX), GX - 1);
    int ihiy = min((int)((bhyc - loy) / VOX), GY - 1);
    int ihiz = min((int)((bhzc - loz) / VOX), GZ - 1);

    int nx = ihix - ilox + 1;
    int ny = ihiy - iloy + 1;
    int nz = ihiz - iloz + 1;

    // symmetric 3x3 inverse (adjugate / det)
    float i00 = c11*c22 - c12*c12;
    float i01 = c02*c12 - c01*c22;
    float i02 = c01*c12 - c02*c11;
    float i11 = c00*c22 - c02*c02;
    float i12 = c01*c02 - c00*c12;
    float i22 = c00*c11 - c01*c01;
    float det = c00*i00 + c01*i01 + c02*i02;
    float rdet = 1.f / det;
    float a00 = i00*rdet, a01 = i01*rdet, a02 = i02*rdet;
    float a11 = i11*rdet, a12 = i12*rdet, a22 = i22*rdet;

    float op = opac[gwarp];
    float f[F_N];
#pragma unroll
    for (int k = 0; k < F_N; k++) f[k] = feat[(size_t)gwarp*F_N + k];

    float* dgrid = out;
    float* fgrid = out + NVOX;

    int npairs = nx * ny;
    for (int p = lane; p < npairs; p += 32) {
        int ox = p / ny;
        int oy = p - ox * ny;
        int ix = ilox + ox;
        int iy = iloy + oy;
        float dx = ((float)ix + 0.5f) * VOX + lox - mx;
        float dy = ((float)iy + 0.5f) * VOX + loy - my;
        float cxy  = a00*dx*dx + a11*dy*dy + 2.f*a01*dx*dy;
        float clin = 2.f*(a02*dx + a12*dy);
        int flatBase = (ix * GY + iy) * GZ + iloz;
        for (int oz = 0; oz < nz; oz++) {
            int iz = iloz + oz;
            float dz = ((float)iz + 0.5f) * VOX + loz - mz;
            float maha = cxy + dz * (clin + a22 * dz);
            float dv = op * __expf(-0.5f * maha);
            atomicAdd(dgrid + flatBase + oz, dv);
            float* fp = fgrid + (size_t)(flatBase + oz) * F_N;
            red_add_v4(fp,     dv*f[0], dv*f[1], dv*f[2], dv*f[3]);
            red_add_v4(fp + 4, dv*f[4], dv*f[5], dv*f[6], dv*f[7]);
        }
    }
}

__global__ void gv_norm_kernel(float* __restrict__ out) {
    int v = blockIdx.x * blockDim.x + threadIdx.x;
    if (v >= NVOX) return;
    float den = out[v];
    float s = 1.f / fmaxf(den, 1e-6f);
    float4* fp = (float4*)(out + NVOX + (size_t)v * F_N);
    float4 a = fp[0], b = fp[1];
    a.x *= s; a.y *= s; a.z *= s; a.w *= s;
    b.x *= s; b.y *= s; b.z *= s; b.w *= s;
    fp[0] = a; fp[1] = b;
}

extern "C" void kernel_launch(void* const* d_in, const int* in_sizes, int n_in,
                              void* d_out, int out_size) {
    const float* means = (const float*)d_in[0];   // (G,3)
    const float* opac  = (const float*)d_in[1];   // (G,1)
    const float* cov   = (const float*)d_in[2];   // (G,3,3)
    const float* feat  = (const float*)d_in[3];   // (G,8)
    float* out = (float*)d_out;                   // [640000 density | 5120000 feats]

    int G = in_sizes[0] / 3;

    int n4 = out_size / 4;
    gv_zero_kernel<<<(n4 + 255) / 256, 256>>>((float4*)out, n4);

    int threads = G * 32;  // one warp per gaussian
    gv_splat_kernel<<<(threads + 255) / 256, 256>>>(means, opac, cov, feat, out, G);

    gv_norm_kernel<<<(NVOX + 255) / 256, 256>>>(out);
}

// round 3
// speedup vs baseline: 1.1369x; 1.1226x over previous
#include <cuda_runtime.h>
#include <math.h>

#define GX 200
#define GY 200
#define GZ 16
#define NVOX (GX*GY*GZ)
#define F_N 8

__device__ __forceinline__ void red_add_v4(float* p, float a, float b, float c, float d) {
    asm volatile("red.global.add.v4.f32 [%0], {%1,%2,%3,%4};"
                 :: "l"(p), "f"(a), "f"(b), "f"(c), "f"(d) : "memory");
}

__global__ void gv_splat_kernel(const float* __restrict__ means,
                                const float* __restrict__ opac,
                                const float* __restrict__ cov,
                                const float* __restrict__ feat,
                                float* __restrict__ out,
                                int G) {
    int gwarp = (blockIdx.x * blockDim.x + threadIdx.x) >> 5;
    if (gwarp >= G) return;
    int lane = threadIdx.x & 31;

    const float lox = -40.f, loy = -40.f, loz = -1.f;
    const float hix =  40.f, hiy =  40.f, hiz =  5.4f;
    const float VOX = 0.4f;

    float mx = means[gwarp*3 + 0];
    float my = means[gwarp*3 + 1];
    float mz = means[gwarp*3 + 2];
    const float* C = cov + (size_t)gwarp * 9;
    float c00 = C[0], c01 = C[1], c02 = C[2];
    float c11 = C[4], c12 = C[5], c22 = C[8];

    float sx = sqrtf(c00), sy = sqrtf(c11), sz = sqrtf(c22);
    float blx = mx - 3.f*sx, bly = my - 3.f*sy, blz = mz - 3.f*sz;
    float bhx = mx + 3.f*sx, bhy = my + 3.f*sy, bhz = mz + 3.f*sz;

    bool valid = (bhx > lox) && (bhy > loy) && (bhz > loz) &&
                 (blx < hix) && (bly < hiy) && (blz < hiz);
    if (!valid) return;

    float blxc = fminf(fmaxf(blx, lox), hix);
    float blyc = fminf(fmaxf(bly, loy), hiy);
    float blzc = fminf(fmaxf(blz, loz), hiz);
    float bhxc = fminf(fmaxf(bhx, lox), hix);
    float bhyc = fminf(fmaxf(bhy, loy), hiy);
    float bhzc = fminf(fmaxf(bhz, loz), hiz);

    int ilox = min((int)((blxc - lox) / VOX), GX - 1);
    int iloy = min((int)((blyc - loy) / VOX), GY - 1);
    int iloz = min((int)((blzc - loz) / VOX), GZ - 1);
    int ihix = min((int)((bhxc - lox) / VOX), GX - 1);
    int ihiy = min((int)((bhyc - loy) / VOX), GY - 1);
    int ihiz = min((int)((bhzc - loz) / VOX), GZ - 1);

    int nx = ihix - ilox + 1;
    int ny = ihiy - iloy + 1;

    // symmetric 3x3 inverse (adjugate / det)
    float i00 = c11*c22 - c12*c12;
    float i01 = c02*c12 - c01*c22;
    float i02 = c01*c12 - c02*c11;
    float i11 = c00*c22 - c02*c02;
    float i12 = c01*c02 - c00*c12;
    float i22 = c00*c11 - c01*c01;
    float det = c00*i00 + c01*i01 + c02*i02;
    float rdet = 1.f / det;
    float a00 = i00*rdet, a01 = i01*rdet, a02 = i02*rdet;
    float a11 = i11*rdet, a12 = i12*rdet, a22 = i22*rdet;

    float op = opac[gwarp];
    float f[F_N];
#pragma unroll
    for (int k = 0; k < F_N; k++) f[k] = feat[(size_t)gwarp*F_N + k];

    float* dgrid = out;
    float* fgrid = out + NVOX;

    int z0 = iloz & ~3;   // aligned start of z quads (GZ=16 -> quads never cross columns)

    int npairs = nx * ny;
    for (int p = lane; p < npairs; p += 32) {
        int ox = p / ny;
        int oy = p - ox * ny;
        int ix = ilox + ox;
        int iy = iloy + oy;
        float dx = ((float)ix + 0.5f) * VOX + lox - mx;
        float dy = ((float)iy + 0.5f) * VOX + loy - my;
        float cxy  = a00*dx*dx + a11*dy*dy + 2.f*a01*dx*dy;
        float clin = 2.f*(a02*dx + a12*dy);
        int colBase = (ix * GY + iy) * GZ;

        for (int zb = z0; zb <= ihiz; zb += 4) {
            float dvq[4];
#pragma unroll
            for (int j = 0; j < 4; j++) {
                int iz = zb + j;
                float dv = 0.f;
                if (iz >= iloz && iz <= ihiz) {
                    float dz = ((float)iz + 0.5f) * VOX + loz - mz;
                    float maha = cxy + dz * (clin + a22 * dz);
                    dv = op * __expf(-0.5f * maha);
                    float* fp = fgrid + (size_t)(colBase + iz) * F_N;
                    red_add_v4(fp,     dv*f[0], dv*f[1], dv*f[2], dv*f[3]);
                    red_add_v4(fp + 4, dv*f[4], dv*f[5], dv*f[6], dv*f[7]);
                }
                dvq[j] = dv;
            }
            // one vector atomic covers 4 consecutive density voxels (16B aligned)
            red_add_v4(dgrid + colBase + zb, dvq[0], dvq[1], dvq[2], dvq[3]);
        }
    }
}

__global__ void gv_norm_kernel(float* __restrict__ out) {
    int v = blockIdx.x * blockDim.x + threadIdx.x;
    if (v >= NVOX) return;
    float den = out[v];
    float s = 1.f / fmaxf(den, 1e-6f);
    float4* fp = (float4*)(out + NVOX + (size_t)v * F_N);
    float4 a = fp[0], b = fp[1];
    a.x *= s; a.y *= s; a.z *= s; a.w *= s;
    b.x *= s; b.y *= s; b.z *= s; b.w *= s;
    fp[0] = a; fp[1] = b;
}

extern "C" void kernel_launch(void* const* d_in, const int* in_sizes, int n_in,
                              void* d_out, int out_size) {
    const float* means = (const float*)d_in[0];   // (G,3)
    const float* opac  = (const float*)d_in[1];   // (G,1)
    const float* cov   = (const float*)d_in[2];   // (G,3,3)
    const float* feat  = (const float*)d_in[3];   // (G,8)
    float* out = (float*)d_out;                   // [640000 density | 5120000 feats]

    int G = in_sizes[0] / 3;

    cudaMemsetAsync(out, 0, (size_t)out_size * sizeof(float));

    int threads = G * 32;  // one warp per gaussian
    gv_splat_kernel<<<(threads + 255) / 256, 256>>>(means, opac, cov, feat, out, G);

    gv_norm_kernel<<<(NVOX + 255) / 256, 256>>>(out);
}

// round 4
// speedup vs baseline: 1.1564x; 1.0172x over previous
#include <cuda_runtime.h>
#include <math.h>

#define GX 200
#define GY 200
#define GZ 16
#define NVOX (GX*GY*GZ)
#define F_N 8

__device__ __forceinline__ void red_add_v4(float* p, float a, float b, float c, float d) {
    asm volatile("red.global.add.v4.f32 [%0], {%1,%2,%3,%4};"
                 :: "l"(p), "f"(a), "f"(b), "f"(c), "f"(d) : "memory");
}

__global__ void gv_splat_kernel(const float* __restrict__ means,
                                const float* __restrict__ opac,
                                const float* __restrict__ cov,
                                const float* __restrict__ feat,
                                float* __restrict__ out,
                                int G) {
    int gwarp = (blockIdx.x * blockDim.x + threadIdx.x) >> 5;
    if (gwarp >= G) return;
    int lane = threadIdx.x & 31;

    const float lox = -40.f, loy = -40.f, loz = -1.f;
    const float hix =  40.f, hiy =  40.f, hiz =  5.4f;
    const float VOX = 0.4f;

    float mx = means[gwarp*3 + 0];
    float my = means[gwarp*3 + 1];
    float mz = means[gwarp*3 + 2];
    const float* C = cov + (size_t)gwarp * 9;
    float c00 = C[0], c01 = C[1], c02 = C[2];
    float c11 = C[4], c12 = C[5], c22 = C[8];

    float sx = sqrtf(c00), sy = sqrtf(c11), sz = sqrtf(c22);
    float blx = mx - 3.f*sx, bly = my - 3.f*sy, blz = mz - 3.f*sz;
    float bhx = mx + 3.f*sx, bhy = my + 3.f*sy, bhz = mz + 3.f*sz;

    bool valid = (bhx > lox) && (bhy > loy) && (bhz > loz) &&
                 (blx < hix) && (bly < hiy) && (blz < hiz);
    if (!valid) return;

    float blxc = fminf(fmaxf(blx, lox), hix);
    float blyc = fminf(fmaxf(bly, loy), hiy);
    float blzc = fminf(fmaxf(blz, loz), hiz);
    float bhxc = fminf(fmaxf(bhx, lox), hix);
    float bhyc = fminf(fmaxf(bhy, loy), hiy);
    float bhzc = fminf(fmaxf(bhz, loz), hiz);

    int ilox = min((int)((blxc - lox) / VOX), GX - 1);
    int iloy = min((int)((blyc - loy) / VOX), GY - 1);
    int iloz = min((int)((blzc - loz) / VOX), GZ - 1);
    int ihix = min((int)((bhxc - lox) / VOX), GX - 1);
    int ihiy = min((int)((bhyc - loy) / VOX), GY - 1);
    int ihiz = min((int)((bhzc - loz) / VOX), GZ - 1);

    int nx = ihix - ilox + 1;
    int ny = ihiy - iloy + 1;

    // symmetric 3x3 inverse (adjugate / det)
    float i00 = c11*c22 - c12*c12;
    float i01 = c02*c12 - c01*c22;
    float i02 = c01*c12 - c02*c11;
    float i11 = c00*c22 - c02*c02;
    float i12 = c01*c02 - c00*c12;
    float i22 = c00*c11 - c01*c01;
    float det = c00*i00 + c01*i01 + c02*i02;
    float rdet = 1.f / det;
    float a00 = i00*rdet, a01 = i01*rdet, a02 = i02*rdet;
    float a11 = i11*rdet, a12 = i12*rdet, a22 = i22*rdet;

    float op = opac[gwarp];
    float f[F_N];
#pragma unroll
    for (int k = 0; k < F_N; k++) f[k] = feat[(size_t)gwarp*F_N + k];

    float* dgrid = out;
    float* fgrid = out + NVOX;

    int z0 = iloz & ~3;   // aligned start of z quads (GZ=16 -> quads never cross columns)

    int npairs = nx * ny;
    for (int p = lane; p < npairs; p += 32) {
        int ox = p / ny;
        int oy = p - ox * ny;
        int ix = ilox + ox;
        int iy = iloy + oy;
        float dx = ((float)ix + 0.5f) * VOX + lox - mx;
        float dy = ((float)iy + 0.5f) * VOX + loy - my;
        float cxy  = a00*dx*dx + a11*dy*dy + 2.f*a01*dx*dy;
        float clin = 2.f*(a02*dx + a12*dy);
        int colBase = (ix * GY + iy) * GZ;

        for (int zb = z0; zb <= ihiz; zb += 4) {
            float dvq[4];
#pragma unroll
            for (int j = 0; j < 4; j++) {
                int iz = zb + j;
                float dv = 0.f;
                if (iz >= iloz && iz <= ihiz) {
                    float dz = ((float)iz + 0.5f) * VOX + loz - mz;
                    float maha = cxy + dz * (clin + a22 * dz);
                    dv = op * __expf(-0.5f * maha);
                    float* fp = fgrid + (size_t)(colBase + iz) * F_N;
                    red_add_v4(fp,     dv*f[0], dv*f[1], dv*f[2], dv*f[3]);
                    red_add_v4(fp + 4, dv*f[4], dv*f[5], dv*f[6], dv*f[7]);
                }
                dvq[j] = dv;
            }
            // one vector atomic covers 4 consecutive density voxels (16B aligned)
            red_add_v4(dgrid + colBase + zb, dvq[0], dvq[1], dvq[2], dvq[3]);
        }
    }
}

// One thread per feature-float4: 2 threads per voxel, maximal MLP.
__global__ void gv_norm_kernel(float* __restrict__ out) {
    int i = blockIdx.x * blockDim.x + threadIdx.x;
    if (i >= NVOX * 2) return;
    int v = i >> 1;
    float den = out[v];
    float s = 1.f / fmaxf(den, 1e-6f);
    float4* fp = (float4*)(out + NVOX) + i;
    float4 a = *fp;
    a.x *= s; a.y *= s; a.z *= s; a.w *= s;
    *fp = a;
}

extern "C" void kernel_launch(void* const* d_in, const int* in_sizes, int n_in,
                              void* d_out, int out_size) {
    const float* means = (const float*)d_in[0];   // (G,3)
    const float* opac  = (const float*)d_in[1];   // (G,1)
    const float* cov   = (const float*)d_in[2];   // (G,3,3)
    const float* feat  = (const float*)d_in[3];   // (G,8)
    float* out = (float*)d_out;                   // [640000 density | 5120000 feats]

    int G = in_sizes[0] / 3;

    cudaMemsetAsync(out, 0, (size_t)out_size * sizeof(float));

    int threads = G * 32;  // one warp per gaussian
    gv_splat_kernel<<<(threads + 255) / 256, 256>>>(means, opac, cov, feat, out, G);

    gv_norm_kernel<<<(NVOX * 2 + 255) / 256, 256>>>(out);
}

// round 5
// speedup vs baseline: 1.1782x; 1.0188x over previous
#include <cuda_runtime.h>
#include <math.h>

#define GX 200
#define GY 200
#define GZ 16
#define NVOX (GX*GY*GZ)
#define F_N 8

__device__ __forceinline__ void red_add_v4(float* p, float a, float b, float c, float d) {
    asm volatile("red.global.add.v4.f32 [%0], {%1,%2,%3,%4};"
                 :: "l"(p), "f"(a), "f"(b), "f"(c), "f"(d) : "memory");
}

__global__ void gv_splat_kernel(const float* __restrict__ means,
                                const float* __restrict__ opac,
                                const float* __restrict__ cov,
                                const float* __restrict__ feat,
                                float* __restrict__ out,
                                int G) {
    int gwarp = (blockIdx.x * blockDim.x + threadIdx.x) >> 5;
    if (gwarp >= G) return;
    int lane = threadIdx.x & 31;

    const float lox = -40.f, loy = -40.f, loz = -1.f;
    const float hix =  40.f, hiy =  40.f, hiz =  5.4f;
    const float VOX = 0.4f;

    float mx = means[gwarp*3 + 0];
    float my = means[gwarp*3 + 1];
    float mz = means[gwarp*3 + 2];
    const float* C = cov + (size_t)gwarp * 9;
    float c00 = C[0], c01 = C[1], c02 = C[2];
    float c11 = C[4], c12 = C[5], c22 = C[8];

    float sx = sqrtf(c00), sy = sqrtf(c11), sz = sqrtf(c22);
    float blx = mx - 3.f*sx, bly = my - 3.f*sy, blz = mz - 3.f*sz;
    float bhx = mx + 3.f*sx, bhy = my + 3.f*sy, bhz = mz + 3.f*sz;

    bool valid = (bhx > lox) && (bhy > loy) && (bhz > loz) &&
                 (blx < hix) && (bly < hiy) && (blz < hiz);
    if (!valid) return;

    float blxc = fminf(fmaxf(blx, lox), hix);
    float blyc = fminf(fmaxf(bly, loy), hiy);
    float blzc = fminf(fmaxf(blz, loz), hiz);
    float bhxc = fminf(fmaxf(bhx, lox), hix);
    float bhyc = fminf(fmaxf(bhy, loy), hiy);
    float bhzc = fminf(fmaxf(bhz, loz), hiz);

    int ilox = min((int)((blxc - lox) / VOX), GX - 1);
    int iloy = min((int)((blyc - loy) / VOX), GY - 1);
    int iloz = min((int)((blzc - loz) / VOX), GZ - 1);
    int ihix = min((int)((bhxc - lox) / VOX), GX - 1);
    int ihiy = min((int)((bhyc - loy) / VOX), GY - 1);
    int ihiz = min((int)((bhzc - loz) / VOX), GZ - 1);

    int nx = ihix - ilox + 1;
    int ny = ihiy - iloy + 1;

    // symmetric 3x3 inverse (adjugate / det)
    float i00 = c11*c22 - c12*c12;
    float i01 = c02*c12 - c01*c22;
    float i02 = c01*c12 - c02*c11;
    float i11 = c00*c22 - c02*c02;
    float i12 = c01*c02 - c00*c12;
    float i22 = c00*c11 - c01*c01;
    float det = c00*i00 + c01*i01 + c02*i02;
    float rdet = 1.f / det;
    float a00 = i00*rdet, a01 = i01*rdet, a02 = i02*rdet;
    float a11 = i11*rdet, a12 = i12*rdet, a22 = i22*rdet;

    float op = opac[gwarp];
    float f[F_N];
#pragma unroll
    for (int k = 0; k < F_N; k++) f[k] = feat[(size_t)gwarp*F_N + k];

    float* dgrid = out;
    float* fgrid = out + NVOX;

    int z0 = iloz & ~3;   // aligned start of z quads (GZ=16 -> quads never cross columns)

    int npairs = nx * ny;
    for (int p = lane; p < npairs; p += 32) {
        int ox = p / ny;
        int oy = p - ox * ny;
        int ix = ilox + ox;
        int iy = iloy + oy;
        float dx = ((float)ix + 0.5f) * VOX + lox - mx;
        float dy = ((float)iy + 0.5f) * VOX + loy - my;
        float cxy  = a00*dx*dx + a11*dy*dy + 2.f*a01*dx*dy;
        float clin = 2.f*(a02*dx + a12*dy);
        int colBase = (ix * GY + iy) * GZ;

        for (int zb = z0; zb <= ihiz; zb += 4) {
            float dvq[4];
#pragma unroll
            for (int j = 0; j < 4; j++) {
                int iz = zb + j;
                float dv = 0.f;
                if (iz >= iloz && iz <= ihiz) {
                    float dz = ((float)iz + 0.5f) * VOX + loz - mz;
                    float maha = cxy + dz * (clin + a22 * dz);
                    dv = op * __expf(-0.5f * maha);
                    float* fp = fgrid + (size_t)(colBase + iz) * F_N;
                    red_add_v4(fp,     dv*f[0], dv*f[1], dv*f[2], dv*f[3]);
                    red_add_v4(fp + 4, dv*f[4], dv*f[5], dv*f[6], dv*f[7]);
                }
                dvq[j] = dv;
            }
            // one vector atomic covers 4 consecutive density voxels (16B aligned)
            red_add_v4(dgrid + colBase + zb, dvq[0], dvq[1], dvq[2], dvq[3]);
        }
    }
}

// One thread per feature-float4: 2 threads per voxel, maximal MLP.
__global__ void gv_norm_kernel(float* __restrict__ out) {
    int i = blockIdx.x * blockDim.x + threadIdx.x;
    if (i >= NVOX * 2) return;
    int v = i >> 1;
    float den = out[v];
    float s = 1.f / fmaxf(den, 1e-6f);
    float4* fp = (float4*)(out + NVOX) + i;
    float4 a = *fp;
    a.x *= s; a.y *= s; a.z *= s; a.w *= s;
    *fp = a;
}

extern "C" void kernel_launch(void* const* d_in, const int* in_sizes, int n_in,
                              void* d_out, int out_size) {
    const float* means = (const float*)d_in[0];   // (G,3)
    const float* opac  = (const float*)d_in[1];   // (G,1)
    const float* cov   = (const float*)d_in[2];   // (G,3,3)
    const float* feat  = (const float*)d_in[3];   // (G,8)
    float* out = (float*)d_out;                   // [640000 density | 5120000 feats]

    int G = in_sizes[0] / 3;

    cudaMemsetAsync(out, 0, (size_t)out_size * sizeof(float));

    int threads = G * 32;  // one warp per gaussian
    gv_splat_kernel<<<(threads + 255) / 256, 256>>>(means, opac, cov, feat, out, G);

    gv_norm_kernel<<<(NVOX * 2 + 255) / 256, 256>>>(out);
}